// round 1
// baseline (speedup 1.0000x reference)
#include <cuda_runtime.h>

// ---------------- problem dims ----------------
#define NNODES 2708
#define NFEAT  4096
#define MDICT  2048
#define NHID   1024
#define NCLS   64
#define PITER  100
#define FITER  20

// ---------------- scratch (device globals; no allocation allowed) ----------------
__device__ float g_G  [(size_t)MDICT * MDICT];   // W^T W
__device__ float g_WtY[(size_t)MDICT * NFEAT];   // W^T x
__device__ float g_Z  [(size_t)MDICT * NFEAT];
__device__ float g_Gm [(size_t)MDICT * NFEAT];   // Gamma
__device__ float g_GZ [(size_t)MDICT * NFEAT];
__device__ float g_xg1[(size_t)NNODES * NHID];
__device__ float g_h  [(size_t)NNODES * NHID];
__device__ float g_hg2[(size_t)NNODES * NCLS];
__device__ float g_o2 [(size_t)NNODES * NCLS];
__device__ float g_xv [2][MDICT];                // power method ping-pong
__device__ double g_pns[PITER];                  // per-iter ||Xn||^2
__device__ double g_rs1[FITER];                  // <Z, GZ>
__device__ double g_rs2[FITER];                  // <Z, WtY>
__device__ double g_yn2;                         // ||Y||^2
__device__ float g_c, g_eta, g_thr, g_lam;

// ---------------- init / zero ----------------
__global__ void k_zero() {
    int t = threadIdx.x;
    if (t < PITER) g_pns[t] = 0.0;
    if (t < FITER) { g_rs1[t] = 0.0; g_rs2[t] = 0.0; }
    if (t == 0) g_yn2 = 0.0;
}

// ---------------- threefry2x32 -> X0 = jax.random.normal(key(1), (1,2048)) ----------------
__device__ __forceinline__ unsigned rotl32(unsigned x, int r) {
    return (x << r) | (x >> (32 - r));
}
__device__ __forceinline__ float bits_to_normal(unsigned b) {
    unsigned fb = (b >> 9) | 0x3F800000u;
    float f01 = __uint_as_float(fb) - 1.0f;           // [0,1)
    const float lo = -0.99999994f;                    // nextafter(-1,0) fp32
    float u = f01 * 2.0f + lo;                        // (hi-lo) rounds to 2.0f
    u = fmaxf(u, lo);
    return 1.41421356237309504880f * erfinvf(u);      // sqrt(2) * erfinv
}
__global__ void k_x0() {
    int j = blockIdx.x * blockDim.x + threadIdx.x;
    if (j >= MDICT / 2) return;
    unsigned x0 = (unsigned)j;
    unsigned x1 = (unsigned)(j + MDICT / 2);
    unsigned ks[3] = {0u, 1u, 0u ^ 1u ^ 0x1BD11BDAu};
    const int rot[2][4] = {{13, 15, 26, 6}, {17, 29, 16, 24}};
    x0 += ks[0]; x1 += ks[1];
#pragma unroll
    for (int i = 0; i < 5; i++) {
#pragma unroll
        for (int rr = 0; rr < 4; rr++) {
            int r = rot[i & 1][rr];
            x0 += x1; x1 = rotl32(x1, r); x1 ^= x0;
        }
        x0 += ks[(i + 1) % 3];
        x1 += ks[(i + 2) % 3] + (unsigned)(i + 1);
    }
    g_xv[0][j]             = bits_to_normal(x0);
    g_xv[0][j + MDICT / 2] = bits_to_normal(x1);
}

// ---------------- ||Y||^2 ----------------
__global__ void k_ynorm(const float* __restrict__ x) {
    size_t n = (size_t)NNODES * NFEAT;
    double s = 0.0;
    for (size_t i = (size_t)blockIdx.x * blockDim.x + threadIdx.x; i < n;
         i += (size_t)gridDim.x * blockDim.x) {
        double v = (double)x[i];
        s += v * v;
    }
    for (int o = 16; o > 0; o >>= 1) s += __shfl_down_sync(0xffffffffu, s, o);
    if ((threadIdx.x & 31) == 0) atomicAdd(&g_yn2, s);
}

// ---------------- generic guarded SGEMM: C = op(A) * B (+bias)(+relu) ----------------
// TA=false: A is MxK row-major.  TA=true: A is KxM row-major (computes A^T B).
// B is KxN row-major. EPI: 0 none, 1 +bias, 2 +bias,relu.
template <bool TA, int EPI>
__global__ __launch_bounds__(256) void sgemm_kernel(
    const float* __restrict__ A, const float* __restrict__ B,
    float* __restrict__ C, int M, int N, int K, const float* __restrict__ bias) {
    const int BM = 128, BN = 128, BK = 8, TM = 8, TN = 8;
    __shared__ float As[BK][BM];
    __shared__ float Bs[BK][BN];
    int tid = threadIdx.x;
    int m0 = blockIdx.y * BM;
    int n0 = blockIdx.x * BN;
    int trow = (tid / 16) * TM;
    int tcol = (tid % 16) * TN;

    float acc[TM][TN];
#pragma unroll
    for (int i = 0; i < TM; i++)
#pragma unroll
        for (int j = 0; j < TN; j++) acc[i][j] = 0.0f;

    for (int k0 = 0; k0 < K; k0 += BK) {
        // ---- load A tile into As[k][m] ----
        if (!TA) {
            int arow = tid >> 1;
            int akb = (tid & 1) * 4;
            int gm = m0 + arow, gk = k0 + akb;
            if (gm < M && gk + 3 < K) {
                float4 v = *reinterpret_cast<const float4*>(A + (size_t)gm * K + gk);
                As[akb + 0][arow] = v.x; As[akb + 1][arow] = v.y;
                As[akb + 2][arow] = v.z; As[akb + 3][arow] = v.w;
            } else {
#pragma unroll
                for (int i = 0; i < 4; i++) {
                    int kk = gk + i;
                    As[akb + i][arow] = (gm < M && kk < K) ? A[(size_t)gm * K + kk] : 0.0f;
                }
            }
        } else {
            int ak = tid >> 5;
            int amb = (tid & 31) * 4;
            int gk = k0 + ak, gm = m0 + amb;
            if (gk < K && gm + 3 < M) {
                float4 v = *reinterpret_cast<const float4*>(A + (size_t)gk * M + gm);
                As[ak][amb + 0] = v.x; As[ak][amb + 1] = v.y;
                As[ak][amb + 2] = v.z; As[ak][amb + 3] = v.w;
            } else {
#pragma unroll
                for (int i = 0; i < 4; i++) {
                    int mm = gm + i;
                    As[ak][amb + i] = (gk < K && mm < M) ? A[(size_t)gk * M + mm] : 0.0f;
                }
            }
        }
        // ---- load B tile into Bs[k][n] ----
        {
            int bk = tid >> 5;
            int bnb = (tid & 31) * 4;
            int gk = k0 + bk, gn = n0 + bnb;
            if (gk < K && gn + 3 < N) {
                float4 v = *reinterpret_cast<const float4*>(B + (size_t)gk * N + gn);
                Bs[bk][bnb + 0] = v.x; Bs[bk][bnb + 1] = v.y;
                Bs[bk][bnb + 2] = v.z; Bs[bk][bnb + 3] = v.w;
            } else {
#pragma unroll
                for (int i = 0; i < 4; i++) {
                    int nn = gn + i;
                    Bs[bk][bnb + i] = (gk < K && nn < N) ? B[(size_t)gk * N + nn] : 0.0f;
                }
            }
        }
        __syncthreads();
#pragma unroll
        for (int kk = 0; kk < BK; kk++) {
            float ar[TM], br[TN];
#pragma unroll
            for (int i = 0; i < TM; i++) ar[i] = As[kk][trow + i];
#pragma unroll
            for (int j = 0; j < TN; j++) br[j] = Bs[kk][tcol + j];
#pragma unroll
            for (int i = 0; i < TM; i++)
#pragma unroll
                for (int j = 0; j < TN; j++) acc[i][j] = fmaf(ar[i], br[j], acc[i][j]);
        }
        __syncthreads();
    }
#pragma unroll
    for (int i = 0; i < TM; i++) {
        int gm = m0 + trow + i;
        if (gm < M) {
#pragma unroll
            for (int j = 0; j < TN; j++) {
                int gn = n0 + tcol + j;
                if (gn < N) {
                    float v = acc[i][j];
                    if (EPI >= 1) v += bias[gn];
                    if (EPI == 2) v = fmaxf(v, 0.0f);
                    C[(size_t)gm * N + gn] = v;
                }
            }
        }
    }
}

// ---------------- power iteration: y = (x/nm_prev) @ G ; accumulate ||y||^2 ----------------
__global__ void k_power(int k) {
    int row = blockIdx.x;
    const float* xin = g_xv[k & 1];
    float* xout = g_xv[(k + 1) & 1];
    const float* grow = g_G + (size_t)row * MDICT;
    float s = 0.0f;
    for (int j = threadIdx.x; j < MDICT; j += blockDim.x) s = fmaf(grow[j], xin[j], s);
    __shared__ float sh[256];
    sh[threadIdx.x] = s;
    __syncthreads();
    for (int off = 128; off > 0; off >>= 1) {
        if (threadIdx.x < off) sh[threadIdx.x] += sh[threadIdx.x + off];
        __syncthreads();
    }
    if (threadIdx.x == 0) {
        double scale = (k == 0) ? 1.0 : 1.0 / sqrt(g_pns[k - 1]);
        float y = (float)(sh[0] * scale);
        xout[row] = y;
        atomicAdd(&g_pns[k], (double)y * (double)y);
    }
}

// ---------------- scalars: c, eta, thresholds, lam parsing ----------------
__global__ void k_scalars(const void* Kp) {
    int iv = *(const int*)Kp;
    float lam;
    if (iv > -1000000 && iv < 1000000) lam = (float)iv;     // int32/int64 scalar
    else lam = *(const float*)Kp;                           // float32 scalar
    g_lam = lam;
    float c = sqrtf((float)g_pns[PITER - 1]);
    g_c = c;
    g_eta = 1.0f / c;
    g_thr = lam / c;
}

// ---------------- Gamma0 = soft(eta * WtY, lam); Z = Gamma0 ----------------
__global__ void k_gamma0() {
    size_t n = (size_t)MDICT * NFEAT;
    float eta = g_eta, lam = g_lam;
    for (size_t i = (size_t)blockIdx.x * blockDim.x + threadIdx.x; i < n;
         i += (size_t)gridDim.x * blockDim.x) {
        float r = eta * g_WtY[i];
        float a = fabsf(r) - lam;
        float gn = (a > 0.0f) ? copysignf(a, r) : 0.0f;
        g_Gm[i] = gn;
        g_Z[i] = gn;
    }
}

// ---------------- fused FISTA update + residual-norm reduction ----------------
__global__ void k_update(float coef, int it) {
    size_t n = (size_t)MDICT * NFEAT;
    float eta = g_eta, thr = g_thr;
    double s1 = 0.0, s2 = 0.0;
    for (size_t i = (size_t)blockIdx.x * blockDim.x + threadIdx.x; i < n;
         i += (size_t)gridDim.x * blockDim.x) {
        float z = g_Z[i], gz = g_GZ[i], wty = g_WtY[i], gm = g_Gm[i];
        s1 += (double)z * (double)gz;
        s2 += (double)z * (double)wty;
        float r = z - eta * (gz - wty);
        float a = fabsf(r) - thr;
        float gn = (a > 0.0f) ? copysignf(a, r) : 0.0f;
        g_Gm[i] = gn;
        g_Z[i] = gn + coef * (gn - gm);
    }
    for (int o = 16; o > 0; o >>= 1) {
        s1 += __shfl_down_sync(0xffffffffu, s1, o);
        s2 += __shfl_down_sync(0xffffffffu, s2, o);
    }
    if ((threadIdx.x & 31) == 0) {
        atomicAdd(&g_rs1[it], s1);
        atomicAdd(&g_rs2[it], s2);
    }
}

// ---------------- norms output ----------------
__global__ void k_norms(float* __restrict__ o) {
    int k = threadIdx.x;
    if (k < FITER) {
        double yn2 = g_yn2;
        double r2 = g_rs1[k] - 2.0 * g_rs2[k] + yn2;
        if (r2 < 0.0) r2 = 0.0;
        o[k] = (float)(sqrt(r2) / sqrt(yn2));
    }
}

// ---------------- copy Gamma to output ----------------
__global__ void k_copy_gamma(float* __restrict__ o) {
    size_t n = (size_t)MDICT * NFEAT;
    for (size_t i = (size_t)blockIdx.x * blockDim.x + threadIdx.x; i < n;
         i += (size_t)gridDim.x * blockDim.x)
        o[i] = g_Gm[i];
}

// ---------------- log_softmax over rows of 64 ----------------
__global__ void k_logsm(const float* __restrict__ in, float* __restrict__ out) {
    int row = blockIdx.x;
    const float* r = in + (size_t)row * NCLS;
    int t = threadIdx.x;  // 32 threads
    float a = r[t], b = r[t + 32];
    float m = fmaxf(a, b);
    for (int o = 16; o > 0; o >>= 1) m = fmaxf(m, __shfl_xor_sync(0xffffffffu, m, o));
    float e = expf(a - m) + expf(b - m);
    for (int o = 16; o > 0; o >>= 1) e += __shfl_xor_sync(0xffffffffu, e, o);
    float lse = logf(e);
    out[(size_t)row * NCLS + t] = a - m - lse;
    out[(size_t)row * NCLS + t + 32] = b - m - lse;
}

// ---------------- launch ----------------
static inline dim3 ggrid(int M, int N) { return dim3((N + 127) / 128, (M + 127) / 128); }

extern "C" void kernel_launch(void* const* d_in, const int* in_sizes, int n_in,
                              void* d_out, int out_size) {
    const float* x   = (const float*)d_in[0];
    const float* adj = (const float*)d_in[1];
    const float* g1w = (const float*)d_in[2];
    const float* g1b = (const float*)d_in[3];
    const float* g2w = (const float*)d_in[4];
    const float* g2b = (const float*)d_in[5];
    const float* W   = (const float*)d_in[6];
    const void*  Kp  = d_in[7];
    float* out = (float*)d_out;

    float* o_logp = out;
    float* o_xdec = out + (size_t)NNODES * NCLS;
    float* o_gam  = o_xdec + (size_t)NNODES * NFEAT;
    float* o_nrm  = o_gam + (size_t)MDICT * NFEAT;

    // device-global scratch addresses
    float *pG, *pWtY, *pZ, *pGm, *pGZ, *pxg1, *ph, *phg2, *po2;
    { void* t; cudaGetSymbolAddress(&t, g_G);   pG   = (float*)t; }
    { void* t; cudaGetSymbolAddress(&t, g_WtY); pWtY = (float*)t; }
    { void* t; cudaGetSymbolAddress(&t, g_Z);   pZ   = (float*)t; }
    { void* t; cudaGetSymbolAddress(&t, g_Gm);  pGm  = (float*)t; }
    { void* t; cudaGetSymbolAddress(&t, g_GZ);  pGZ  = (float*)t; }
    { void* t; cudaGetSymbolAddress(&t, g_xg1); pxg1 = (float*)t; }
    { void* t; cudaGetSymbolAddress(&t, g_h);   ph   = (float*)t; }
    { void* t; cudaGetSymbolAddress(&t, g_hg2); phg2 = (float*)t; }
    { void* t; cudaGetSymbolAddress(&t, g_o2);  po2  = (float*)t; }

    // momentum coefficients (fp32, matches reference scalar math)
    float coefs[FITER];
    {
        float t = 1.0f;
        for (int i = 0; i < FITER; i++) {
            float tn = (1.0f + sqrtf(1.0f + 4.0f * t * t)) / 2.0f;
            coefs[i] = (t - 1.0f) / tn;
            t = tn;
        }
    }

    k_zero<<<1, 256>>>();
    k_x0<<<4, 256>>>();
    k_ynorm<<<512, 256>>>(x);

    // G = W^T W   (2048x2048, K=2708)
    sgemm_kernel<true, 0><<<ggrid(MDICT, MDICT), 256>>>(W, W, pG, MDICT, MDICT, NNODES, nullptr);
    // WtY = W^T x (2048x4096, K=2708)
    sgemm_kernel<true, 0><<<ggrid(MDICT, NFEAT), 256>>>(W, x, pWtY, MDICT, NFEAT, NNODES, nullptr);

    // power method on G (exact 100-iteration trajectory, threefry X0)
    for (int k = 0; k < PITER; k++) k_power<<<MDICT, 256>>>(k);

    k_scalars<<<1, 1>>>(Kp);
    k_gamma0<<<1024, 256>>>();

    // FISTA main loop: GZ = G @ Z, then fused soft-threshold/momentum/norm update
    for (int it = 0; it < FITER; it++) {
        sgemm_kernel<false, 0><<<ggrid(MDICT, NFEAT), 256>>>(pG, pZ, pGZ, MDICT, NFEAT, MDICT, nullptr);
        k_update<<<1024, 256>>>(coefs[it], it);
    }

    k_norms<<<1, 32>>>(o_nrm);
    k_copy_gamma<<<1024, 256>>>(o_gam);

    // x_dec = W @ Gamma (2708x4096, K=2048) -> directly to output
    sgemm_kernel<false, 0><<<ggrid(NNODES, NFEAT), 256>>>(W, pGm, o_xdec, NNODES, NFEAT, MDICT, nullptr);
    // xg1 = x_dec @ gc1_w (2708x1024, K=4096)
    sgemm_kernel<false, 0><<<ggrid(NNODES, NHID), 256>>>(o_xdec, g1w, pxg1, NNODES, NHID, NFEAT, nullptr);
    // h = relu(adj @ xg1 + b1) (2708x1024, K=2708)
    sgemm_kernel<false, 2><<<ggrid(NNODES, NHID), 256>>>(adj, pxg1, ph, NNODES, NHID, NNODES, g1b);
    // hg2 = h @ gc2_w (2708x64, K=1024)
    sgemm_kernel<false, 0><<<ggrid(NNODES, NCLS), 256>>>(ph, g2w, phg2, NNODES, NCLS, NHID, nullptr);
    // out2 = adj @ hg2 + b2 (2708x64, K=2708)
    sgemm_kernel<false, 1><<<ggrid(NNODES, NCLS), 256>>>(adj, phg2, po2, NNODES, NCLS, NNODES, g2b);
    // log_softmax rows
    k_logsm<<<NNODES, 32>>>(po2, o_logp);
}

// round 5
// speedup vs baseline: 1.5530x; 1.5530x over previous
#include <cuda_runtime.h>
#include <cuda_bf16.h>
#include <cstdint>

// ---------------- problem dims ----------------
#define NNODES 2708
#define NFEAT  4096
#define MDICT  2048
#define NHID   1024
#define NCLS   64
#define PITER  100
#define FITER  20

// ---------------- scratch (device globals; no allocation allowed) ----------------
// NOTE: FISTA elementwise state is stored TRANSPOSED: [NFEAT][MDICT]
__device__ float g_G  [(size_t)MDICT * MDICT];   // W^T W (fp32, row-major, symmetric)
__device__ float g_WtY[(size_t)NFEAT * MDICT];   // (W^T x)^T = x^T W  [n][m]
__device__ float g_Z  [(size_t)NFEAT * MDICT];   // Z^T
__device__ float g_Gm [(size_t)NFEAT * MDICT];   // Gamma^T
__device__ float g_GZ [(size_t)NFEAT * MDICT];   // (G Z)^T
__device__ __nv_bfloat16 g_Ghi[(size_t)MDICT * MDICT];
__device__ __nv_bfloat16 g_Glo[(size_t)MDICT * MDICT];
__device__ __nv_bfloat16 g_Zhi[(size_t)NFEAT * MDICT];
__device__ __nv_bfloat16 g_Zlo[(size_t)NFEAT * MDICT];
__device__ float g_xg1[(size_t)NNODES * NHID];
__device__ float g_h  [(size_t)NNODES * NHID];
__device__ float g_hg2[(size_t)NNODES * NCLS];
__device__ float g_o2 [(size_t)NNODES * NCLS];
__device__ float g_xv [2][MDICT];                // power method ping-pong
__device__ double g_pns[PITER];                  // per-iter ||Xn||^2
__device__ double g_rs1[FITER];                  // <Z, GZ>
__device__ double g_rs2[FITER];                  // <Z, WtY>
__device__ double g_yn2;                         // ||Y||^2
__device__ float g_c, g_eta, g_thr, g_lam;

// ---------------- init / zero ----------------
__global__ void k_zero() {
    int t = threadIdx.x;
    if (t < PITER) g_pns[t] = 0.0;
    if (t < FITER) { g_rs1[t] = 0.0; g_rs2[t] = 0.0; }
    if (t == 0) g_yn2 = 0.0;
}

// ---------------- threefry2x32 -> X0 = jax.random.normal(key(1), (1,2048)) ----------------
__device__ __forceinline__ unsigned rotl32(unsigned x, int r) {
    return (x << r) | (x >> (32 - r));
}
__device__ __forceinline__ float bits_to_normal(unsigned b) {
    unsigned fb = (b >> 9) | 0x3F800000u;
    float f01 = __uint_as_float(fb) - 1.0f;
    const float lo = -0.99999994f;
    float u = f01 * 2.0f + lo;
    u = fmaxf(u, lo);
    return 1.41421356237309504880f * erfinvf(u);
}
__global__ void k_x0() {
    int j = blockIdx.x * blockDim.x + threadIdx.x;
    if (j >= MDICT / 2) return;
    unsigned x0 = (unsigned)j;
    unsigned x1 = (unsigned)(j + MDICT / 2);
    unsigned ks[3] = {0u, 1u, 0u ^ 1u ^ 0x1BD11BDAu};
    const int rot[2][4] = {{13, 15, 26, 6}, {17, 29, 16, 24}};
    x0 += ks[0]; x1 += ks[1];
#pragma unroll
    for (int i = 0; i < 5; i++) {
#pragma unroll
        for (int rr = 0; rr < 4; rr++) {
            int r = rot[i & 1][rr];
            x0 += x1; x1 = rotl32(x1, r); x1 ^= x0;
        }
        x0 += ks[(i + 1) % 3];
        x1 += ks[(i + 2) % 3] + (unsigned)(i + 1);
    }
    g_xv[0][j]             = bits_to_normal(x0);
    g_xv[0][j + MDICT / 2] = bits_to_normal(x1);
}

// ---------------- ||Y||^2 ----------------
__global__ void k_ynorm(const float* __restrict__ x) {
    size_t n = (size_t)NNODES * NFEAT;
    double s = 0.0;
    for (size_t i = (size_t)blockIdx.x * blockDim.x + threadIdx.x; i < n;
         i += (size_t)gridDim.x * blockDim.x) {
        double v = (double)x[i];
        s += v * v;
    }
    for (int o = 16; o > 0; o >>= 1) s += __shfl_down_sync(0xffffffffu, s, o);
    if ((threadIdx.x & 31) == 0) atomicAdd(&g_yn2, s);
}

// ---------------- generic guarded SGEMM (fp32, SIMT) ----------------
template <bool TA, int EPI>
__global__ __launch_bounds__(256) void sgemm_kernel(
    const float* __restrict__ A, const float* __restrict__ B,
    float* __restrict__ C, int M, int N, int K, const float* __restrict__ bias) {
    const int BM = 128, BN = 128, BK = 8, TM = 8, TN = 8;
    __shared__ float As[BK][BM];
    __shared__ float Bs[BK][BN];
    int tid = threadIdx.x;
    int m0 = blockIdx.y * BM;
    int n0 = blockIdx.x * BN;
    int trow = (tid / 16) * TM;
    int tcol = (tid % 16) * TN;

    float acc[TM][TN];
#pragma unroll
    for (int i = 0; i < TM; i++)
#pragma unroll
        for (int j = 0; j < TN; j++) acc[i][j] = 0.0f;

    for (int k0 = 0; k0 < K; k0 += BK) {
        if (!TA) {
            int arow = tid >> 1;
            int akb = (tid & 1) * 4;
            int gm = m0 + arow, gk = k0 + akb;
            if (gm < M && gk + 3 < K) {
                float4 v = *reinterpret_cast<const float4*>(A + (size_t)gm * K + gk);
                As[akb + 0][arow] = v.x; As[akb + 1][arow] = v.y;
                As[akb + 2][arow] = v.z; As[akb + 3][arow] = v.w;
            } else {
#pragma unroll
                for (int i = 0; i < 4; i++) {
                    int kk = gk + i;
                    As[akb + i][arow] = (gm < M && kk < K) ? A[(size_t)gm * K + kk] : 0.0f;
                }
            }
        } else {
            int ak = tid >> 5;
            int amb = (tid & 31) * 4;
            int gk = k0 + ak, gm = m0 + amb;
            if (gk < K && gm + 3 < M) {
                float4 v = *reinterpret_cast<const float4*>(A + (size_t)gk * M + gm);
                As[ak][amb + 0] = v.x; As[ak][amb + 1] = v.y;
                As[ak][amb + 2] = v.z; As[ak][amb + 3] = v.w;
            } else {
#pragma unroll
                for (int i = 0; i < 4; i++) {
                    int mm = gm + i;
                    As[ak][amb + i] = (gk < K && mm < M) ? A[(size_t)gk * M + mm] : 0.0f;
                }
            }
        }
        {
            int bk = tid >> 5;
            int bnb = (tid & 31) * 4;
            int gk = k0 + bk, gn = n0 + bnb;
            if (gk < K && gn + 3 < N) {
                float4 v = *reinterpret_cast<const float4*>(B + (size_t)gk * N + gn);
                Bs[bk][bnb + 0] = v.x; Bs[bk][bnb + 1] = v.y;
                Bs[bk][bnb + 2] = v.z; Bs[bk][bnb + 3] = v.w;
            } else {
#pragma unroll
                for (int i = 0; i < 4; i++) {
                    int nn = gn + i;
                    Bs[bk][bnb + i] = (gk < K && nn < N) ? B[(size_t)gk * N + nn] : 0.0f;
                }
            }
        }
        __syncthreads();
#pragma unroll
        for (int kk = 0; kk < BK; kk++) {
            float ar[TM], br[TN];
#pragma unroll
            for (int i = 0; i < TM; i++) ar[i] = As[kk][trow + i];
#pragma unroll
            for (int j = 0; j < TN; j++) br[j] = Bs[kk][tcol + j];
#pragma unroll
            for (int i = 0; i < TM; i++)
#pragma unroll
                for (int j = 0; j < TN; j++) acc[i][j] = fmaf(ar[i], br[j], acc[i][j]);
        }
        __syncthreads();
    }
#pragma unroll
    for (int i = 0; i < TM; i++) {
        int gm = m0 + trow + i;
        if (gm < M) {
#pragma unroll
            for (int j = 0; j < TN; j++) {
                int gn = n0 + tcol + j;
                if (gn < N) {
                    float v = acc[i][j];
                    if (EPI >= 1) v += bias[gn];
                    if (EPI == 2) v = fmaxf(v, 0.0f);
                    C[(size_t)gm * N + gn] = v;
                }
            }
        }
    }
}

// ---------------- split fp32 -> bf16 hi/lo ----------------
__device__ __forceinline__ void split2(float v, __nv_bfloat16& h, __nv_bfloat16& l) {
    h = __float2bfloat16(v);
    l = __float2bfloat16(v - __bfloat162float(h));
}

__global__ void k_splitG() {
    size_t n = (size_t)MDICT * MDICT;
    for (size_t i = (size_t)blockIdx.x * blockDim.x + threadIdx.x; i < n;
         i += (size_t)gridDim.x * blockDim.x) {
        __nv_bfloat16 h, l;
        split2(g_G[i], h, l);
        g_Ghi[i] = h;
        g_Glo[i] = l;
    }
}

// ---------------- power iteration (fp32 G) ----------------
__global__ void k_power(int k) {
    int row = blockIdx.x;
    const float* xin = g_xv[k & 1];
    float* xout = g_xv[(k + 1) & 1];
    const float* grow = g_G + (size_t)row * MDICT;
    float s = 0.0f;
    for (int j = threadIdx.x; j < MDICT; j += blockDim.x) s = fmaf(grow[j], xin[j], s);
    __shared__ float sh[256];
    sh[threadIdx.x] = s;
    __syncthreads();
    for (int off = 128; off > 0; off >>= 1) {
        if (threadIdx.x < off) sh[threadIdx.x] += sh[threadIdx.x + off];
        __syncthreads();
    }
    if (threadIdx.x == 0) {
        double scale = (k == 0) ? 1.0 : 1.0 / sqrt(g_pns[k - 1]);
        float y = (float)(sh[0] * scale);
        xout[row] = y;
        atomicAdd(&g_pns[k], (double)y * (double)y);
    }
}

// ---------------- scalars ----------------
__global__ void k_scalars(const void* Kp) {
    int iv = *(const int*)Kp;
    float lam;
    if (iv > -1000000 && iv < 1000000) lam = (float)iv;
    else lam = *(const float*)Kp;
    g_lam = lam;
    float c = sqrtf((float)g_pns[PITER - 1]);
    g_c = c;
    g_eta = 1.0f / c;
    g_thr = lam / c;
}

// ---------------- Gamma0 (transposed layout) ----------------
__global__ void k_gamma0() {
    size_t n = (size_t)MDICT * NFEAT;
    float eta = g_eta, lam = g_lam;
    for (size_t i = (size_t)blockIdx.x * blockDim.x + threadIdx.x; i < n;
         i += (size_t)gridDim.x * blockDim.x) {
        float r = eta * g_WtY[i];
        float a = fabsf(r) - lam;
        float gn = (a > 0.0f) ? copysignf(a, r) : 0.0f;
        g_Gm[i] = gn;
        g_Z[i] = gn;
        __nv_bfloat16 h, l;
        split2(gn, h, l);
        g_Zhi[i] = h;
        g_Zlo[i] = l;
    }
}

// ---------------- fused FISTA update (transposed layout) ----------------
__global__ void k_update(float coef, int it) {
    size_t n = (size_t)MDICT * NFEAT;
    float eta = g_eta, thr = g_thr;
    double s1 = 0.0, s2 = 0.0;
    for (size_t i = (size_t)blockIdx.x * blockDim.x + threadIdx.x; i < n;
         i += (size_t)gridDim.x * blockDim.x) {
        float z = g_Z[i], gz = g_GZ[i], wty = g_WtY[i], gm = g_Gm[i];
        s1 += (double)z * (double)gz;
        s2 += (double)z * (double)wty;
        float r = z - eta * (gz - wty);
        float a = fabsf(r) - thr;
        float gn = (a > 0.0f) ? copysignf(a, r) : 0.0f;
        g_Gm[i] = gn;
        float zn = gn + coef * (gn - gm);
        g_Z[i] = zn;
        __nv_bfloat16 h, l;
        split2(zn, h, l);
        g_Zhi[i] = h;
        g_Zlo[i] = l;
    }
    for (int o = 16; o > 0; o >>= 1) {
        s1 += __shfl_down_sync(0xffffffffu, s1, o);
        s2 += __shfl_down_sync(0xffffffffu, s2, o);
    }
    if ((threadIdx.x & 31) == 0) {
        atomicAdd(&g_rs1[it], s1);
        atomicAdd(&g_rs2[it], s2);
    }
}

// ================= HMMA (mma.sync) GZ^T = Z^T @ G, bf16 hi/lo split ==============
// C[n][m] = sum_k A[n][k] * B[m][k];  A = Z^T [4096 x 2048], B = G [2048 x 2048]
// Tile: 128(n) x 128(m) per CTA, BK=32, 8 warps each 32(n) x 64(m).
// SMEM tiles stride 40 bf16 (80B) -> ldmatrix conflict-free.
#define GZ_TILE_B   10240           // 128 rows * 80 B
#define GZ_STAGE_B  (4 * GZ_TILE_B) // Ahi, Alo, Bhi, Blo
#define GZ_SMEM_B   (2 * GZ_STAGE_B)

__device__ __forceinline__ uint32_t smem_u32(const void* p) {
    uint32_t a;
    asm("{ .reg .u64 t; cvta.to.shared.u64 t, %1; cvt.u32.u64 %0, t; }" : "=r"(a) : "l"(p));
    return a;
}
#define CPA16(dst, src) \
    asm volatile("cp.async.cg.shared.global [%0], [%1], 16;" :: "r"(dst), "l"(src))
#define CPA_COMMIT() asm volatile("cp.async.commit_group;")
#define CPA_WAIT1()  asm volatile("cp.async.wait_group 1;")
#define CPA_WAIT0()  asm volatile("cp.async.wait_group 0;")

__device__ __forceinline__ void ldsm4(uint32_t* r, uint32_t addr) {
    asm volatile("ldmatrix.sync.aligned.m8n8.x4.shared.b16 {%0,%1,%2,%3}, [%4];"
                 : "=r"(r[0]), "=r"(r[1]), "=r"(r[2]), "=r"(r[3]) : "r"(addr));
}
__device__ __forceinline__ void mma16816(float* c, const uint32_t* a, const uint32_t* b) {
    asm volatile(
        "mma.sync.aligned.m16n8k16.row.col.f32.bf16.bf16.f32 "
        "{%0,%1,%2,%3}, {%4,%5,%6,%7}, {%8,%9}, {%0,%1,%2,%3};"
        : "+f"(c[0]), "+f"(c[1]), "+f"(c[2]), "+f"(c[3])
        : "r"(a[0]), "r"(a[1]), "r"(a[2]), "r"(a[3]), "r"(b[0]), "r"(b[1]));
}

__device__ __forceinline__ void gz_issue(
    uint32_t buf, const __nv_bfloat16* __restrict__ Ahi, const __nv_bfloat16* __restrict__ Alo,
    const __nv_bfloat16* __restrict__ Bhi, const __nv_bfloat16* __restrict__ Blo,
    int n0, int m0, int k0, int tid) {
    int row = tid >> 1;
    int cb = (tid & 1) * 32;                       // byte offset within row's 64B
    size_t aoff = ((size_t)(n0 + row) * MDICT + k0) * 2 + cb;
    size_t boff = ((size_t)(m0 + row) * MDICT + k0) * 2 + cb;
    uint32_t so = (uint32_t)(row * 80 + cb);
    const char* pah = (const char*)Ahi + aoff;
    const char* pal = (const char*)Alo + aoff;
    const char* pbh = (const char*)Bhi + boff;
    const char* pbl = (const char*)Blo + boff;
    CPA16(buf + 0 * GZ_TILE_B + so,      pah);
    CPA16(buf + 0 * GZ_TILE_B + so + 16, pah + 16);
    CPA16(buf + 1 * GZ_TILE_B + so,      pal);
    CPA16(buf + 1 * GZ_TILE_B + so + 16, pal + 16);
    CPA16(buf + 2 * GZ_TILE_B + so,      pbh);
    CPA16(buf + 2 * GZ_TILE_B + so + 16, pbh + 16);
    CPA16(buf + 3 * GZ_TILE_B + so,      pbl);
    CPA16(buf + 3 * GZ_TILE_B + so + 16, pbl + 16);
}

__global__ __launch_bounds__(256, 2) void gz_mma_kernel(
    const __nv_bfloat16* __restrict__ Ahi, const __nv_bfloat16* __restrict__ Alo,
    const __nv_bfloat16* __restrict__ Bhi, const __nv_bfloat16* __restrict__ Blo,
    float* __restrict__ Cout) {
    extern __shared__ char dynsmem[];
    uint32_t sb = smem_u32(dynsmem);
    int tid = threadIdx.x;
    int lane = tid & 31;
    int wid = tid >> 5;
    int wr = wid >> 1;           // n quadrant (0..3): rows wr*32
    int wc = wid & 1;            // m half (0..1): cols wc*64
    int m0 = blockIdx.x * 128;
    int n0 = blockIdx.y * 128;

    float acc[2][8][4];
#pragma unroll
    for (int i = 0; i < 2; i++)
#pragma unroll
        for (int j = 0; j < 8; j++)
#pragma unroll
            for (int q = 0; q < 4; q++) acc[i][j][q] = 0.0f;

    const int NS = MDICT / 32;   // 64 stages
    gz_issue(sb, Ahi, Alo, Bhi, Blo, n0, m0, 0, tid);
    CPA_COMMIT();

    // precompute per-lane ldmatrix row/col pieces
    int amat = lane >> 3;                 // 0..3
    int ar8 = lane & 7;
    int a_row_in = (amat & 1) * 8 + ar8;  // + mi*16 + wr*32
    int a_col = (amat >> 1) * 8;          // + ks*16
    int b_row_in = ((amat >> 1) ? 8 : 0) + ar8;   // + 2nj*8 + wc*64
    int b_col = (amat & 1) * 8;           // + ks*16

#pragma unroll 1
    for (int s = 0; s < NS; s++) {
        if (s + 1 < NS) {
            gz_issue(sb + ((s + 1) & 1) * GZ_STAGE_B, Ahi, Alo, Bhi, Blo,
                     n0, m0, (s + 1) * 32, tid);
            CPA_COMMIT();
            CPA_WAIT1();
        } else {
            CPA_WAIT0();
        }
        __syncthreads();
        uint32_t buf = sb + (s & 1) * GZ_STAGE_B;
#pragma unroll
        for (int ks = 0; ks < 2; ks++) {
            uint32_t ah[2][4], al[2][4];
#pragma unroll
            for (int mi = 0; mi < 2; mi++) {
                uint32_t arow = (uint32_t)(wr * 32 + mi * 16 + a_row_in);
                uint32_t acol = (uint32_t)(ks * 16 + a_col);
                uint32_t off = arow * 80 + acol * 2;
                ldsm4(ah[mi], buf + 0 * GZ_TILE_B + off);
                ldsm4(al[mi], buf + 1 * GZ_TILE_B + off);
            }
#pragma unroll
            for (int nj = 0; nj < 4; nj++) {
                uint32_t brow = (uint32_t)(wc * 64 + nj * 16 + b_row_in);
                uint32_t bcol = (uint32_t)(ks * 16 + b_col);
                uint32_t off = brow * 80 + bcol * 2;
                uint32_t bh[4], bl[4];
                ldsm4(bh, buf + 2 * GZ_TILE_B + off);
                ldsm4(bl, buf + 3 * GZ_TILE_B + off);
#pragma unroll
                for (int p = 0; p < 2; p++) {
#pragma unroll
                    for (int mi = 0; mi < 2; mi++) {
                        mma16816(acc[mi][nj * 2 + p], ah[mi], bh + 2 * p);
                        mma16816(acc[mi][nj * 2 + p], ah[mi], bl + 2 * p);
                        mma16816(acc[mi][nj * 2 + p], al[mi], bh + 2 * p);
                    }
                }
            }
        }
        __syncthreads();
    }

    // epilogue: store fp32
#pragma unroll
    for (int mi = 0; mi < 2; mi++) {
#pragma unroll
        for (int nf = 0; nf < 8; nf++) {
            int rown = n0 + wr * 32 + mi * 16 + (lane >> 2);
            int colm = m0 + wc * 64 + nf * 8 + (lane & 3) * 2;
            float* p = Cout + (size_t)rown * MDICT + colm;
            p[0] = acc[mi][nf][0];
            p[1] = acc[mi][nf][1];
            float* p2 = p + 8 * MDICT;
            p2[0] = acc[mi][nf][2];
            p2[1] = acc[mi][nf][3];
        }
    }
}

// ---------------- norms output ----------------
__global__ void k_norms(float* __restrict__ o) {
    int k = threadIdx.x;
    if (k < FITER) {
        double yn2 = g_yn2;
        double r2 = g_rs1[k] - 2.0 * g_rs2[k] + yn2;
        if (r2 < 0.0) r2 = 0.0;
        o[k] = (float)(sqrt(r2) / sqrt(yn2));
    }
}

// ---------------- transpose Gamma^T [NFEAT][MDICT] -> Gamma [MDICT][NFEAT] ----------------
__global__ void k_transpose(const float* __restrict__ in, float* __restrict__ out) {
    __shared__ float t[32][33];
    int mb = blockIdx.x * 32;
    int nb = blockIdx.y * 32;
    int tx = threadIdx.x, ty = threadIdx.y;
#pragma unroll
    for (int j = 0; j < 4; j++) {
        int nn = nb + ty + j * 8;
        t[ty + j * 8][tx] = in[(size_t)nn * MDICT + mb + tx];
    }
    __syncthreads();
#pragma unroll
    for (int j = 0; j < 4; j++) {
        int mm = mb + ty + j * 8;
        out[(size_t)mm * NFEAT + nb + tx] = t[tx][ty + j * 8];
    }
}

// ---------------- log_softmax over rows of 64 ----------------
__global__ void k_logsm(const float* __restrict__ in, float* __restrict__ out) {
    int row = blockIdx.x;
    const float* r = in + (size_t)row * NCLS;
    int t = threadIdx.x;
    float a = r[t], b = r[t + 32];
    float m = fmaxf(a, b);
    for (int o = 16; o > 0; o >>= 1) m = fmaxf(m, __shfl_xor_sync(0xffffffffu, m, o));
    float e = expf(a - m) + expf(b - m);
    for (int o = 16; o > 0; o >>= 1) e += __shfl_xor_sync(0xffffffffu, e, o);
    float lse = logf(e);
    out[(size_t)row * NCLS + t] = a - m - lse;
    out[(size_t)row * NCLS + t + 32] = b - m - lse;
}

// ---------------- launch ----------------
static inline dim3 ggrid(int M, int N) { return dim3((N + 127) / 128, (M + 127) / 128); }

extern "C" void kernel_launch(void* const* d_in, const int* in_sizes, int n_in,
                              void* d_out, int out_size) {
    const float* x   = (const float*)d_in[0];
    const float* adj = (const float*)d_in[1];
    const float* g1w = (const float*)d_in[2];
    const float* g1b = (const float*)d_in[3];
    const float* g2w = (const float*)d_in[4];
    const float* g2b = (const float*)d_in[5];
    const float* W   = (const float*)d_in[6];
    const void*  Kp  = d_in[7];
    float* out = (float*)d_out;

    float* o_logp = out;
    float* o_xdec = out + (size_t)NNODES * NCLS;
    float* o_gam  = o_xdec + (size_t)NNODES * NFEAT;
    float* o_nrm  = o_gam + (size_t)MDICT * NFEAT;

    float *pG, *pWtYt, *pZt, *pGmt, *pGZt, *pxg1, *ph, *phg2, *po2;
    __nv_bfloat16 *pGhi, *pGlo, *pZhi, *pZlo;
    { void* t; cudaGetSymbolAddress(&t, g_G);   pG    = (float*)t; }
    { void* t; cudaGetSymbolAddress(&t, g_WtY); pWtYt = (float*)t; }
    { void* t; cudaGetSymbolAddress(&t, g_Z);   pZt   = (float*)t; }
    { void* t; cudaGetSymbolAddress(&t, g_Gm);  pGmt  = (float*)t; }
    { void* t; cudaGetSymbolAddress(&t, g_GZ);  pGZt  = (float*)t; }
    { void* t; cudaGetSymbolAddress(&t, g_Ghi); pGhi  = (__nv_bfloat16*)t; }
    { void* t; cudaGetSymbolAddress(&t, g_Glo); pGlo  = (__nv_bfloat16*)t; }
    { void* t; cudaGetSymbolAddress(&t, g_Zhi); pZhi  = (__nv_bfloat16*)t; }
    { void* t; cudaGetSymbolAddress(&t, g_Zlo); pZlo  = (__nv_bfloat16*)t; }
    { void* t; cudaGetSymbolAddress(&t, g_xg1); pxg1  = (float*)t; }
    { void* t; cudaGetSymbolAddress(&t, g_h);   ph    = (float*)t; }
    { void* t; cudaGetSymbolAddress(&t, g_hg2); phg2  = (float*)t; }
    { void* t; cudaGetSymbolAddress(&t, g_o2);  po2   = (float*)t; }

    cudaFuncSetAttribute(gz_mma_kernel, cudaFuncAttributeMaxDynamicSharedMemorySize,
                         GZ_SMEM_B);

    float coefs[FITER];
    {
        float t = 1.0f;
        for (int i = 0; i < FITER; i++) {
            float tn = (1.0f + sqrtf(1.0f + 4.0f * t * t)) / 2.0f;
            coefs[i] = (t - 1.0f) / tn;
            t = tn;
        }
    }

    k_zero<<<1, 256>>>();
    k_x0<<<4, 256>>>();
    k_ynorm<<<512, 256>>>(x);

    // G = W^T W   (2048x2048, K=2708)
    sgemm_kernel<true, 0><<<ggrid(MDICT, MDICT), 256>>>(W, W, pG, MDICT, MDICT, NNODES, nullptr);
    k_splitG<<<1024, 256>>>();
    // WtY^T = x^T W (4096x2048, K=2708)
    sgemm_kernel<true, 0><<<ggrid(NFEAT, MDICT), 256>>>(x, W, pWtYt, NFEAT, MDICT, NNODES, nullptr);

    for (int k = 0; k < PITER; k++) k_power<<<MDICT, 256>>>(k);

    k_scalars<<<1, 1>>>(Kp);
    k_gamma0<<<1024, 256>>>();

    // FISTA: GZ^T = Z^T @ G via mma.sync bf16 hi/lo split
    dim3 gzgrid(MDICT / 128, NFEAT / 128);  // (16, 32)
    for (int it = 0; it < FITER; it++) {
        gz_mma_kernel<<<gzgrid, 256, GZ_SMEM_B>>>(pZhi, pZlo, pGhi, pGlo, pGZt);
        k_update<<<1024, 256>>>(coefs[it], it);
    }

    k_norms<<<1, 32>>>(o_nrm);
    k_transpose<<<dim3(MDICT / 32, NFEAT / 32), dim3(32, 8)>>>(pGmt, o_gam);

    // x_dec = W @ Gamma (2708x4096, K=2048)
    sgemm_kernel<false, 0><<<ggrid(NNODES, NFEAT), 256>>>(W, o_gam, o_xdec, NNODES, NFEAT, MDICT, nullptr);
    // xg1 = x_dec @ gc1_w (2708x1024, K=4096)
    sgemm_kernel<false, 0><<<ggrid(NNODES, NHID), 256>>>(o_xdec, g1w, pxg1, NNODES, NHID, NFEAT, nullptr);
    // h = relu(adj @ xg1 + b1) (2708x1024, K=2708)
    sgemm_kernel<false, 2><<<ggrid(NNODES, NHID), 256>>>(adj, pxg1, ph, NNODES, NHID, NNODES, g1b);
    // hg2 = h @ gc2_w (2708x64, K=1024)
    sgemm_kernel<false, 0><<<ggrid(NNODES, NCLS), 256>>>(ph, g2w, phg2, NNODES, NCLS, NHID, nullptr);
    // out2 = adj @ hg2 + b2 (2708x64, K=2708)
    sgemm_kernel<false, 1><<<ggrid(NNODES, NCLS), 256>>>(adj, phg2, po2, NNODES, NCLS, NNODES, g2b);
    k_logsm<<<NNODES, 32>>>(po2, o_logp);
}

// round 6
// speedup vs baseline: 3.4312x; 2.2094x over previous
#include <cuda_runtime.h>
#include <cuda_bf16.h>
#include <cstdint>

// ---------------- problem dims ----------------
#define NNODES 2708
#define NFEAT  4096
#define MDICT  2048
#define NHID   1024
#define NCLS   64
#define PITER  100
#define FITER  20

#define NPAD   2816            // NNODES padded to 128
#define KNODE  2720            // NNODES padded to 32 (85 k-blocks)
#define KB_NODE 85
#define KB_MD  64              // MDICT/32
#define KB_NF  128             // NFEAT/32
#define KB_NH  32              // NHID/32

// packed layout: [kb][rows][32 bf16] with swizzle chunk' = ((c>>3) + (r>>1)) & 3
#define PKELEMS(kbs, rows) ((size_t)(kbs) * (rows) * 32)

// ---------------- scratch (device globals) ----------------
__device__ float g_G  [(size_t)MDICT * MDICT];
__device__ float g_WtY[(size_t)NFEAT * MDICT];
__device__ float g_Z  [(size_t)NFEAT * MDICT];
__device__ float g_Gm [(size_t)NFEAT * MDICT];
__device__ float g_GZ [(size_t)NFEAT * MDICT];
__device__ float g_o2 [(size_t)NNODES * NCLS];
__device__ float g_xv [2][MDICT];
__device__ double g_pns[PITER];
__device__ double g_rs1[FITER];
__device__ double g_rs2[FITER];
__device__ double g_yn2;
__device__ float g_c, g_eta, g_thr, g_lam;

// packed bf16 hi/lo operand buffers
__device__ __nv_bfloat16 g_WtP [2][PKELEMS(KB_NODE, MDICT)];
__device__ __nv_bfloat16 g_WP  [2][PKELEMS(KB_MD,   NPAD)];
__device__ __nv_bfloat16 g_XtP [2][PKELEMS(KB_NODE, NFEAT)];
__device__ __nv_bfloat16 g_AdjP[2][PKELEMS(KB_NODE, NPAD)];
__device__ __nv_bfloat16 g_G1wtP[2][PKELEMS(KB_NF,  NHID)];
__device__ __nv_bfloat16 g_G2wtP[2][PKELEMS(KB_NH,  128)];
__device__ __nv_bfloat16 g_GP  [2][PKELEMS(KB_MD,   MDICT)];
__device__ __nv_bfloat16 g_ZtP [2][PKELEMS(KB_MD,   NFEAT)];
__device__ __nv_bfloat16 g_GmtP[2][PKELEMS(KB_MD,   NFEAT)];
__device__ __nv_bfloat16 g_XdP [2][PKELEMS(KB_NF,   NPAD)];
__device__ __nv_bfloat16 g_Xg1tP[2][PKELEMS(KB_NODE, NHID)];
__device__ __nv_bfloat16 g_HP  [2][PKELEMS(KB_NH,   NPAD)];
__device__ __nv_bfloat16 g_Hg2tP[2][PKELEMS(KB_NODE, 128)];

// ---------------- PTX helpers ----------------
__device__ __forceinline__ uint32_t smem_u32(const void* p) {
    uint32_t a;
    asm("{ .reg .u64 t; cvta.to.shared.u64 t, %1; cvt.u32.u64 %0, t; }" : "=r"(a) : "l"(p));
    return a;
}
#define MBARRIER_INIT(mb, cnt) \
    asm volatile("mbarrier.init.shared.b64 [%0], %1;" :: "r"(mb), "r"((uint32_t)(cnt)) : "memory")
#define MBAR_EXPECT(mb, n) \
    asm volatile("mbarrier.arrive.expect_tx.shared.b64 _, [%0], %1;" :: "r"(mb), "r"((uint32_t)(n)) : "memory")
#define MBARRIER_WAIT_PARITY(mb_, par_) do { \
    uint32_t _mbar = (uint32_t)(mb_); \
    uint32_t _parity = (uint32_t)(par_); \
    uint32_t _done; \
    asm volatile( \
        "{\n\t.reg .pred p;\n\t" \
        "mbarrier.try_wait.parity.acquire.cta.shared::cta.b64 p, [%1], %2;\n\t" \
        "selp.b32 %0, 1, 0, p;\n\t}" \
        : "=r"(_done) : "r"(_mbar), "r"(_parity) : "memory"); \
    if (!_done) { \
        asm volatile( \
            "{\n\t.reg .pred P1;\n\t" \
            "WAIT_LOOP_%=:\n\t" \
            "mbarrier.try_wait.parity.acquire.cta.shared::cta.b64 P1, [%0], %1, 0x989680;\n\t" \
            "@P1 bra.uni WAIT_DONE_%=;\n\t" \
            "bra.uni WAIT_LOOP_%=;\n\t" \
            "WAIT_DONE_%=:\n\t}" \
            :: "r"(_mbar), "r"(_parity) : "memory"); \
    } \
} while(0)

__device__ __forceinline__ void bulk_cp(uint32_t dst, const void* src, uint32_t bytes, uint32_t mbar) {
    asm volatile(
        "cp.async.bulk.shared::cluster.global.mbarrier::complete_tx::bytes [%0], [%1], %2, [%3];"
        :: "r"(dst), "l"(src), "r"(bytes), "r"(mbar) : "memory");
}
__device__ __forceinline__ void ldsm4(uint32_t* r, uint32_t addr) {
    asm volatile("ldmatrix.sync.aligned.m8n8.x4.shared.b16 {%0,%1,%2,%3}, [%4];"
                 : "=r"(r[0]), "=r"(r[1]), "=r"(r[2]), "=r"(r[3]) : "r"(addr));
}
__device__ __forceinline__ void mma16816(float* c, const uint32_t* a, const uint32_t* b) {
    asm volatile(
        "mma.sync.aligned.m16n8k16.row.col.f32.bf16.bf16.f32 "
        "{%0,%1,%2,%3}, {%4,%5,%6,%7}, {%8,%9}, {%0,%1,%2,%3};"
        : "+f"(c[0]), "+f"(c[1]), "+f"(c[2]), "+f"(c[3])
        : "r"(a[0]), "r"(a[1]), "r"(a[2]), "r"(a[3]), "r"(b[0]), "r"(b[1]));
}
__device__ __forceinline__ void split2(float v, __nv_bfloat16& h, __nv_bfloat16& l) {
    h = __float2bfloat16(v);
    l = __float2bfloat16(v - __bfloat162float(h));
}

// ---------------- init / zero ----------------
__global__ void k_zero() {
    int t = threadIdx.x;
    if (t < PITER) g_pns[t] = 0.0;
    if (t < FITER) { g_rs1[t] = 0.0; g_rs2[t] = 0.0; }
    if (t == 0) g_yn2 = 0.0;
}

// ---------------- threefry X0 ----------------
__device__ __forceinline__ unsigned rotl32(unsigned x, int r) {
    return (x << r) | (x >> (32 - r));
}
__device__ __forceinline__ float bits_to_normal(unsigned b) {
    unsigned fb = (b >> 9) | 0x3F800000u;
    float f01 = __uint_as_float(fb) - 1.0f;
    const float lo = -0.99999994f;
    float u = f01 * 2.0f + lo;
    u = fmaxf(u, lo);
    return 1.41421356237309504880f * erfinvf(u);
}
__global__ void k_x0() {
    int j = blockIdx.x * blockDim.x + threadIdx.x;
    if (j >= MDICT / 2) return;
    unsigned x0 = (unsigned)j;
    unsigned x1 = (unsigned)(j + MDICT / 2);
    unsigned ks[3] = {0u, 1u, 0u ^ 1u ^ 0x1BD11BDAu};
    const int rot[2][4] = {{13, 15, 26, 6}, {17, 29, 16, 24}};
    x0 += ks[0]; x1 += ks[1];
#pragma unroll
    for (int i = 0; i < 5; i++) {
#pragma unroll
        for (int rr = 0; rr < 4; rr++) {
            int r = rot[i & 1][rr];
            x0 += x1; x1 = rotl32(x1, r); x1 ^= x0;
        }
        x0 += ks[(i + 1) % 3];
        x1 += ks[(i + 2) % 3] + (unsigned)(i + 1);
    }
    g_xv[0][j]             = bits_to_normal(x0);
    g_xv[0][j + MDICT / 2] = bits_to_normal(x1);
}

// ---------------- ||Y||^2 ----------------
__global__ void k_ynorm(const float* __restrict__ x) {
    size_t n = (size_t)NNODES * NFEAT;
    double s = 0.0;
    for (size_t i = (size_t)blockIdx.x * blockDim.x + threadIdx.x; i < n;
         i += (size_t)gridDim.x * blockDim.x) {
        double v = (double)x[i];
        s += v * v;
    }
    for (int o = 16; o > 0; o >>= 1) s += __shfl_down_sync(0xffffffffu, s, o);
    if ((threadIdx.x & 31) == 0) atomicAdd(&g_yn2, s);
}

// ---------------- pack kernels ----------------
// no-transpose: in fp32 [R][ld] -> packed [kb][OPR][32], kb over columns
__global__ void k_pack(const float* __restrict__ in, int R, int Creal, int ld,
                       __nv_bfloat16* __restrict__ Ohi, __nv_bfloat16* __restrict__ Olo,
                       int OPR) {
    int kb = blockIdx.x;
    int r = blockIdx.y * 32 + (threadIdx.x >> 2);
    int ch = threadIdx.x & 3;
    int c0 = kb * 32 + ch * 8;
    float v[8];
#pragma unroll
    for (int e = 0; e < 8; e++) {
        int c = c0 + e;
        v[e] = (r < R && c < Creal) ? in[(size_t)r * ld + c] : 0.0f;
    }
    __nv_bfloat16 h[8], l[8];
#pragma unroll
    for (int e = 0; e < 8; e++) split2(v[e], h[e], l[e]);
    int chp = (ch + (r >> 1)) & 3;
    size_t byte = (((size_t)kb * OPR + r) * 64) + (size_t)chp * 16;
    *reinterpret_cast<uint4*>((char*)Ohi + byte) = *reinterpret_cast<uint4*>(h);
    *reinterpret_cast<uint4*>((char*)Olo + byte) = *reinterpret_cast<uint4*>(l);
}

// transpose: in fp32 [R][ld], out packed rows = columns of in, K over R
__global__ void k_packT(const float* __restrict__ in, int R, int Creal, int ld,
                        __nv_bfloat16* __restrict__ Ohi, __nv_bfloat16* __restrict__ Olo,
                        int OPR) {
    __shared__ float t[32][33];
    int gn0 = blockIdx.x * 32;   // k dim (in rows)
    int gc0 = blockIdx.y * 32;   // out rows (in cols)
    int tx = threadIdx.x & 31, ty = threadIdx.x >> 5;
#pragma unroll
    for (int jj = 0; jj < 4; jj++) {
        int r = gn0 + ty + jj * 8;
        int c = gc0 + tx;
        t[ty + jj * 8][tx] = (r < R && c < Creal) ? in[(size_t)r * ld + c] : 0.0f;
    }
    __syncthreads();
    int u = threadIdx.x & 127;
    bool isHi = threadIdx.x < 128;
    int cl = u >> 2, ch = u & 3;
    int row = gc0 + cl;
    __nv_bfloat16 w[8];
#pragma unroll
    for (int e = 0; e < 8; e++) {
        float v = t[ch * 8 + e][cl];
        __nv_bfloat16 hh = __float2bfloat16(v);
        w[e] = isHi ? hh : __float2bfloat16(v - __bfloat162float(hh));
    }
    int chp = (ch + (row >> 1)) & 3;
    size_t byte = (((size_t)(gn0 >> 5) * OPR + row) * 64) + (size_t)chp * 16;
    *reinterpret_cast<uint4*>((char*)(isHi ? Ohi : Olo) + byte) = *reinterpret_cast<uint4*>(w);
}

// ---------------- universal HMMA GEMM: C[i][j] = sum_k A[i][k]*B[j][k] ----------------
// OUT bits: 1=bias, 2=relu, 4=fp32 C, 8=packed split same-orientation, 16=packed split transposed
#define HG_STAGE_B 32768
#define HG_SMEM_B  (3 * HG_STAGE_B + 64)

template <int OUT>
__global__ __launch_bounds__(256, 2) void hgemm(
    const __nv_bfloat16* __restrict__ Ahi, const __nv_bfloat16* __restrict__ Alo,
    const __nv_bfloat16* __restrict__ Bhi, const __nv_bfloat16* __restrict__ Blo,
    int AR, int BR, int Kpad,
    float* __restrict__ C, int ldc, int Mreal, int Nreal, const float* __restrict__ bias,
    __nv_bfloat16* __restrict__ Ohi, __nv_bfloat16* __restrict__ Olo, int OPR, int OKmax) {
    extern __shared__ __align__(128) char smem[];
    uint32_t sb = smem_u32(smem);
    uint32_t mb = sb + 3 * HG_STAGE_B;
    int tid = threadIdx.x;
    int lane = tid & 31;
    int wid = tid >> 5;
    int wr = wid >> 1;
    int wc = wid & 1;
    int j0 = blockIdx.x * 128;   // C cols (B rows)
    int i0 = blockIdx.y * 128;   // C rows (A rows)
    int NS = Kpad >> 5;

    if (tid == 0) {
        MBARRIER_INIT(mb + 0, 1);
        MBARRIER_INIT(mb + 8, 1);
        MBARRIER_INIT(mb + 16, 1);
    }
    __syncthreads();

    // producer: issue stage s (one k-block) as 4 bulk copies of 8KB
    auto issue = [&](int s) {
        int b = s % 3;
        uint32_t mbar = mb + b * 8;
        uint32_t d = sb + (uint32_t)b * HG_STAGE_B;
        MBAR_EXPECT(mbar, HG_STAGE_B);
        size_t ao = ((size_t)s * AR + i0) * 64;
        size_t bo = ((size_t)s * BR + j0) * 64;
        bulk_cp(d + 0,     (const char*)Ahi + ao, 8192, mbar);
        bulk_cp(d + 8192,  (const char*)Alo + ao, 8192, mbar);
        bulk_cp(d + 16384, (const char*)Bhi + bo, 8192, mbar);
        bulk_cp(d + 24576, (const char*)Blo + bo, 8192, mbar);
    };
    if (tid == 0) { issue(0); issue(1); }

    float acc[2][8][4];
#pragma unroll
    for (int i = 0; i < 2; i++)
#pragma unroll
        for (int j = 0; j < 8; j++)
#pragma unroll
            for (int q = 0; q < 4; q++) acc[i][j][q] = 0.0f;

    int amat = lane >> 3;
    int ar8 = lane & 7;
    int a_row_in = (amat & 1) * 8 + ar8;
    int a_col = (amat >> 1) * 8;
    int b_row_in = ((amat >> 1) ? 8 : 0) + ar8;
    int b_col = (amat & 1) * 8;

#pragma unroll 1
    for (int s = 0; s < NS; s++) {
        if (tid == 0 && s + 2 < NS) issue(s + 2);
        MBARRIER_WAIT_PARITY(mb + (s % 3) * 8, (s / 3) & 1);
        uint32_t tbuf = sb + (uint32_t)(s % 3) * HG_STAGE_B;
#pragma unroll
        for (int ks = 0; ks < 2; ks++) {
            uint32_t ah[2][4], al[2][4];
#pragma unroll
            for (int mi = 0; mi < 2; mi++) {
                int r = wr * 32 + mi * 16 + a_row_in;
                int chunk = ks * 2 + (a_col >> 3);
                uint32_t addr = tbuf + (uint32_t)(r * 64 + (((chunk + (r >> 1)) & 3) << 4));
                ldsm4(ah[mi], addr);
                ldsm4(al[mi], addr + 8192);
            }
#pragma unroll
            for (int nj = 0; nj < 4; nj++) {
                int rb = wc * 64 + nj * 16 + b_row_in;
                int chunkb = ks * 2 + (b_col >> 3);
                uint32_t baddr = tbuf + 16384u +
                    (uint32_t)(rb * 64 + (((chunkb + (rb >> 1)) & 3) << 4));
                uint32_t bh[4], bl[4];
                ldsm4(bh, baddr);
                ldsm4(bl, baddr + 8192);
#pragma unroll
                for (int p = 0; p < 2; p++) {
#pragma unroll
                    for (int mi = 0; mi < 2; mi++) {
                        mma16816(acc[mi][nj * 2 + p], ah[mi], bh + 2 * p);
                        mma16816(acc[mi][nj * 2 + p], ah[mi], bl + 2 * p);
                        mma16816(acc[mi][nj * 2 + p], al[mi], bh + 2 * p);
                    }
                }
            }
        }
        __syncthreads();
    }

    // ---------------- epilogue ----------------
#pragma unroll
    for (int mi = 0; mi < 2; mi++) {
#pragma unroll
        for (int nf = 0; nf < 8; nf++) {
            int r0 = i0 + wr * 32 + mi * 16 + (lane >> 2);
            int c0 = j0 + wc * 64 + nf * 8 + (lane & 3) * 2;
#pragma unroll
            for (int half = 0; half < 2; half++) {
                int rr = r0 + half * 8;
                float va = acc[mi][nf][half * 2 + 0];
                float vb = acc[mi][nf][half * 2 + 1];
                if (OUT & 1) {
                    va += (c0 < Nreal) ? bias[c0] : 0.0f;
                    vb += (c0 + 1 < Nreal) ? bias[c0 + 1] : 0.0f;
                }
                if (OUT & 2) { va = fmaxf(va, 0.0f); vb = fmaxf(vb, 0.0f); }
                if (OUT & 4) {
                    if (rr < Mreal) {
                        if (c0 < Nreal) C[(size_t)rr * ldc + c0] = va;
                        if (c0 + 1 < Nreal) C[(size_t)rr * ldc + c0 + 1] = vb;
                    }
                }
                float za = (rr < Mreal && c0 < Nreal) ? va : 0.0f;
                float zb = (rr < Mreal && c0 + 1 < Nreal) ? vb : 0.0f;
                if (OUT & 8) {
                    int kb = c0 >> 5, cc = c0 & 31;
                    int chp = ((cc >> 3) + (rr >> 1)) & 3;
                    size_t byte = (((size_t)kb * OPR + rr) * 64) + (size_t)chp * 16 + (cc & 7) * 2;
                    __nv_bfloat16 ha, la, hb, lb;
                    split2(za, ha, la);
                    split2(zb, hb, lb);
                    __nv_bfloat162 hh; hh.x = ha; hh.y = hb;
                    __nv_bfloat162 ll; ll.x = la; ll.y = lb;
                    *reinterpret_cast<__nv_bfloat162*>((char*)Ohi + byte) = hh;
                    *reinterpret_cast<__nv_bfloat162*>((char*)Olo + byte) = ll;
                }
                if (OUT & 16) {
                    if (rr < OKmax) {
                        int kb = rr >> 5, cc = rr & 31;
#pragma unroll
                        for (int e = 0; e < 2; e++) {
                            int rowt = c0 + e;
                            float v = e ? zb : za;
                            int chp = ((cc >> 3) + (rowt >> 1)) & 3;
                            size_t byte = (((size_t)kb * OPR + rowt) * 64) +
                                          (size_t)chp * 16 + (cc & 7) * 2;
                            __nv_bfloat16 h, l;
                            split2(v, h, l);
                            *reinterpret_cast<__nv_bfloat16*>((char*)Ohi + byte) = h;
                            *reinterpret_cast<__nv_bfloat16*>((char*)Olo + byte) = l;
                        }
                    }
                }
            }
        }
    }
}

// ---------------- power iteration ----------------
__global__ void k_power(int k) {
    int row = blockIdx.x;
    const float* xin = g_xv[k & 1];
    float* xout = g_xv[(k + 1) & 1];
    const float* grow = g_G + (size_t)row * MDICT;
    float s = 0.0f;
    for (int j = threadIdx.x; j < MDICT; j += blockDim.x) s = fmaf(grow[j], xin[j], s);
    __shared__ float sh[256];
    sh[threadIdx.x] = s;
    __syncthreads();
    for (int off = 128; off > 0; off >>= 1) {
        if (threadIdx.x < off) sh[threadIdx.x] += sh[threadIdx.x + off];
        __syncthreads();
    }
    if (threadIdx.x == 0) {
        double scale = (k == 0) ? 1.0 : 1.0 / sqrt(g_pns[k - 1]);
        float y = (float)(sh[0] * scale);
        xout[row] = y;
        atomicAdd(&g_pns[k], (double)y * (double)y);
    }
}

// ---------------- scalars ----------------
__global__ void k_scalars(const void* Kp) {
    int iv = *(const int*)Kp;
    float lam;
    if (iv > -1000000 && iv < 1000000) lam = (float)iv;
    else lam = *(const float*)Kp;
    g_lam = lam;
    float c = sqrtf((float)g_pns[PITER - 1]);
    g_c = c;
    g_eta = 1.0f / c;
    g_thr = lam / c;
}

// ---------------- Gamma0 (transposed layout, packed Zt write) ----------------
__global__ void k_gamma0() {
    int n = blockIdx.x;
    int c8 = threadIdx.x * 8;
    size_t base = (size_t)n * MDICT + c8;
    float eta = g_eta, lam = g_lam;
    float4 w0 = *reinterpret_cast<const float4*>(g_WtY + base);
    float4 w1 = *reinterpret_cast<const float4*>(g_WtY + base + 4);
    float wv[8] = {w0.x, w0.y, w0.z, w0.w, w1.x, w1.y, w1.z, w1.w};
    float gv[8];
    __nv_bfloat16 h[8], l[8];
#pragma unroll
    for (int e = 0; e < 8; e++) {
        float r = eta * wv[e];
        float a = fabsf(r) - lam;
        float gn = (a > 0.0f) ? copysignf(a, r) : 0.0f;
        gv[e] = gn;
        split2(gn, h[e], l[e]);
    }
    *reinterpret_cast<float4*>(g_Gm + base) = make_float4(gv[0], gv[1], gv[2], gv[3]);
    *reinterpret_cast<float4*>(g_Gm + base + 4) = make_float4(gv[4], gv[5], gv[6], gv[7]);
    *reinterpret_cast<float4*>(g_Z + base) = make_float4(gv[0], gv[1], gv[2], gv[3]);
    *reinterpret_cast<float4*>(g_Z + base + 4) = make_float4(gv[4], gv[5], gv[6], gv[7]);
    int kb = c8 >> 5;
    int ch = (c8 & 31) >> 3;
    int chp = (ch + (n >> 1)) & 3;
    size_t byte = (((size_t)kb * NFEAT + n) * 64) + (size_t)chp * 16;
    *reinterpret_cast<uint4*>((char*)g_ZtP[0] + byte) = *reinterpret_cast<uint4*>(h);
    *reinterpret_cast<uint4*>((char*)g_ZtP[1] + byte) = *reinterpret_cast<uint4*>(l);
}

// ---------------- fused FISTA update ----------------
__global__ void k_update(float coef, int it) {
    int n = blockIdx.x;
    int c8 = threadIdx.x * 8;
    size_t base = (size_t)n * MDICT + c8;
    float eta = g_eta, thr = g_thr;
    float4 z0 = *reinterpret_cast<const float4*>(g_Z + base);
    float4 z1 = *reinterpret_cast<const float4*>(g_Z + base + 4);
    float4 q0 = *reinterpret_cast<const float4*>(g_GZ + base);
    float4 q1 = *reinterpret_cast<const float4*>(g_GZ + base + 4);
    float4 w0 = *reinterpret_cast<const float4*>(g_WtY + base);
    float4 w1 = *reinterpret_cast<const float4*>(g_WtY + base + 4);
    float4 m0 = *reinterpret_cast<const float4*>(g_Gm + base);
    float4 m1 = *reinterpret_cast<const float4*>(g_Gm + base + 4);
    float zv[8] = {z0.x, z0.y, z0.z, z0.w, z1.x, z1.y, z1.z, z1.w};
    float qv[8] = {q0.x, q0.y, q0.z, q0.w, q1.x, q1.y, q1.z, q1.w};
    float wv[8] = {w0.x, w0.y, w0.z, w0.w, w1.x, w1.y, w1.z, w1.w};
    float mv[8] = {m0.x, m0.y, m0.z, m0.w, m1.x, m1.y, m1.z, m1.w};
    double s1 = 0.0, s2 = 0.0;
    float gnew[8], znew[8];
    __nv_bfloat16 h[8], l[8];
#pragma unroll
    for (int e = 0; e < 8; e++) {
        s1 += (double)zv[e] * (double)qv[e];
        s2 += (double)zv[e] * (double)wv[e];
        float r = zv[e] - eta * (qv[e] - wv[e]);
        float a = fabsf(r) - thr;
        float gn = (a > 0.0f) ? copysignf(a, r) : 0.0f;
        gnew[e] = gn;
        float zn = gn + coef * (gn - mv[e]);
        znew[e] = zn;
        split2(zn, h[e], l[e]);
    }
    *reinterpret_cast<float4*>(g_Gm + base) = make_float4(gnew[0], gnew[1], gnew[2], gnew[3]);
    *reinterpret_cast<float4*>(g_Gm + base + 4) = make_float4(gnew[4], gnew[5], gnew[6], gnew[7]);
    *reinterpret_cast<float4*>(g_Z + base) = make_float4(znew[0], znew[1], znew[2], znew[3]);
    *reinterpret_cast<float4*>(g_Z + base + 4) = make_float4(znew[4], znew[5], znew[6], znew[7]);
    int kb = c8 >> 5;
    int ch = (c8 & 31) >> 3;
    int chp = (ch + (n >> 1)) & 3;
    size_t byte = (((size_t)kb * NFEAT + n) * 64) + (size_t)chp * 16;
    *reinterpret_cast<uint4*>((char*)g_ZtP[0] + byte) = *reinterpret_cast<uint4*>(h);
    *reinterpret_cast<uint4*>((char*)g_ZtP[1] + byte) = *reinterpret_cast<uint4*>(l);
    for (int o = 16; o > 0; o >>= 1) {
        s1 += __shfl_down_sync(0xffffffffu, s1, o);
        s2 += __shfl_down_sync(0xffffffffu, s2, o);
    }
    if ((threadIdx.x & 31) == 0) {
        atomicAdd(&g_rs1[it], s1);
        atomicAdd(&g_rs2[it], s2);
    }
}

// ---------------- norms output ----------------
__global__ void k_norms(float* __restrict__ o) {
    int k = threadIdx.x;
    if (k < FITER) {
        double yn2 = g_yn2;
        double r2 = g_rs1[k] - 2.0 * g_rs2[k] + yn2;
        if (r2 < 0.0) r2 = 0.0;
        o[k] = (float)(sqrt(r2) / sqrt(yn2));
    }
}

// ---------------- transpose Gamma^T -> Gamma (output) ----------------
__global__ void k_transpose(const float* __restrict__ in, float* __restrict__ out) {
    __shared__ float t[32][33];
    int mb = blockIdx.x * 32;
    int nb = blockIdx.y * 32;
    int tx = threadIdx.x, ty = threadIdx.y;
#pragma unroll
    for (int j = 0; j < 4; j++) {
        int nn = nb + ty + j * 8;
        t[ty + j * 8][tx] = in[(size_t)nn * MDICT + mb + tx];
    }
    __syncthreads();
#pragma unroll
    for (int j = 0; j < 4; j++) {
        int mm = mb + ty + j * 8;
        out[(size_t)mm * NFEAT + nb + tx] = t[tx][ty + j * 8];
    }
}

// ---------------- log_softmax ----------------
__global__ void k_logsm(const float* __restrict__ in, float* __restrict__ out) {
    int row = blockIdx.x;
    const float* r = in + (size_t)row * NCLS;
    int t = threadIdx.x;
    float a = r[t], b = r[t + 32];
    float m = fmaxf(a, b);
    for (int o = 16; o > 0; o >>= 1) m = fmaxf(m, __shfl_xor_sync(0xffffffffu, m, o));
    float e = expf(a - m) + expf(b - m);
    for (int o = 16; o > 0; o >>= 1) e += __shfl_xor_sync(0xffffffffu, e, o);
    float lse = logf(e);
    out[(size_t)row * NCLS + t] = a - m - lse;
    out[(size_t)row * NCLS + t + 32] = b - m - lse;
}

// ---------------- launch ----------------
extern "C" void kernel_launch(void* const* d_in, const int* in_sizes, int n_in,
                              void* d_out, int out_size) {
    const float* x   = (const float*)d_in[0];
    const float* adj = (const float*)d_in[1];
    const float* g1w = (const float*)d_in[2];
    const float* g1b = (const float*)d_in[3];
    const float* g2w = (const float*)d_in[4];
    const float* g2b = (const float*)d_in[5];
    const float* W   = (const float*)d_in[6];
    const void*  Kp  = d_in[7];
    float* out = (float*)d_out;

    float* o_logp = out;
    float* o_xdec = out + (size_t)NNODES * NCLS;
    float* o_gam  = o_xdec + (size_t)NNODES * NFEAT;
    float* o_nrm  = o_gam + (size_t)MDICT * NFEAT;

    float *pG, *pWtYt, *pGmt, *pGZt, *po2;
    { void* t; cudaGetSymbolAddress(&t, g_G);   pG    = (float*)t; }
    { void* t; cudaGetSymbolAddress(&t, g_WtY); pWtYt = (float*)t; }
    { void* t; cudaGetSymbolAddress(&t, g_Gm);  pGmt  = (float*)t; }
    { void* t; cudaGetSymbolAddress(&t, g_GZ);  pGZt  = (float*)t; }
    { void* t; cudaGetSymbolAddress(&t, g_o2);  po2   = (float*)t; }

    __nv_bfloat16 *WtP[2], *WP[2], *XtP[2], *AdjP[2], *G1wtP[2], *G2wtP[2], *GP[2],
                  *ZtP[2], *GmtP[2], *XdP[2], *Xg1tP[2], *HP[2], *Hg2tP[2];
#define GETSYM2(sym, var, kbs, rows) { void* t_; cudaGetSymbolAddress(&t_, sym); \
    var[0] = (__nv_bfloat16*)t_; var[1] = var[0] + PKELEMS(kbs, rows); }
    GETSYM2(g_WtP,   WtP,   KB_NODE, MDICT);
    GETSYM2(g_WP,    WP,    KB_MD,   NPAD);
    GETSYM2(g_XtP,   XtP,   KB_NODE, NFEAT);
    GETSYM2(g_AdjP,  AdjP,  KB_NODE, NPAD);
    GETSYM2(g_G1wtP, G1wtP, KB_NF,   NHID);
    GETSYM2(g_G2wtP, G2wtP, KB_NH,   128);
    GETSYM2(g_GP,    GP,    KB_MD,   MDICT);
    GETSYM2(g_ZtP,   ZtP,   KB_MD,   NFEAT);
    GETSYM2(g_GmtP,  GmtP,  KB_MD,   NFEAT);
    GETSYM2(g_XdP,   XdP,   KB_NF,   NPAD);
    GETSYM2(g_Xg1tP, Xg1tP, KB_NODE, NHID);
    GETSYM2(g_HP,    HP,    KB_NH,   NPAD);
    GETSYM2(g_Hg2tP, Hg2tP, KB_NODE, 128);
#undef GETSYM2

    cudaFuncSetAttribute(hgemm<12>, cudaFuncAttributeMaxDynamicSharedMemorySize, HG_SMEM_B);
    cudaFuncSetAttribute(hgemm<4>,  cudaFuncAttributeMaxDynamicSharedMemorySize, HG_SMEM_B);
    cudaFuncSetAttribute(hgemm<16>, cudaFuncAttributeMaxDynamicSharedMemorySize, HG_SMEM_B);
    cudaFuncSetAttribute(hgemm<11>, cudaFuncAttributeMaxDynamicSharedMemorySize, HG_SMEM_B);
    cudaFuncSetAttribute(hgemm<5>,  cudaFuncAttributeMaxDynamicSharedMemorySize, HG_SMEM_B);

    float coefs[FITER];
    {
        float t = 1.0f;
        for (int i = 0; i < FITER; i++) {
            float tn = (1.0f + sqrtf(1.0f + 4.0f * t * t)) / 2.0f;
            coefs[i] = (t - 1.0f) / tn;
            t = tn;
        }
    }

    k_zero<<<1, 256>>>();
    k_x0<<<4, 256>>>();
    k_ynorm<<<512, 256>>>(x);

    // ---- packs of inputs ----
    k_packT<<<dim3(KB_NODE, MDICT / 32), 256>>>(W, NNODES, MDICT, MDICT, WtP[0], WtP[1], MDICT);
    k_packT<<<dim3(KB_NODE, NFEAT / 32), 256>>>(x, NNODES, NFEAT, NFEAT, XtP[0], XtP[1], NFEAT);
    k_pack <<<dim3(KB_MD, NPAD / 32), 128>>>(W, NNODES, MDICT, MDICT, WP[0], WP[1], NPAD);
    k_pack <<<dim3(KB_NODE, NPAD / 32), 128>>>(adj, NNODES, NNODES, NNODES, AdjP[0], AdjP[1], NPAD);
    k_packT<<<dim3(KB_NF, NHID / 32), 256>>>(g1w, NFEAT, NHID, NHID, G1wtP[0], G1wtP[1], NHID);
    k_packT<<<dim3(KB_NH, 128 / 32), 256>>>(g2w, NHID, NCLS, NCLS, G2wtP[0], G2wtP[1], 128);

    // ---- G = W^T W (fp32 out + packed split out) ----
    hgemm<12><<<dim3(16, 16), 256, HG_SMEM_B>>>(
        WtP[0], WtP[1], WtP[0], WtP[1], MDICT, MDICT, KNODE,
        pG, MDICT, MDICT, MDICT, nullptr, GP[0], GP[1], MDICT, 0);
    // ---- WtY^T = x^T W ----
    hgemm<4><<<dim3(16, 32), 256, HG_SMEM_B>>>(
        XtP[0], XtP[1], WtP[0], WtP[1], NFEAT, MDICT, KNODE,
        pWtYt, MDICT, NFEAT, MDICT, nullptr, nullptr, nullptr, 0, 0);

    for (int k = 0; k < PITER; k++) k_power<<<MDICT, 256>>>(k);
    k_scalars<<<1, 1>>>(Kp);
    k_gamma0<<<NFEAT, 256>>>();

    // ---- FISTA loop ----
    for (int it = 0; it < FITER; it++) {
        hgemm<4><<<dim3(16, 32), 256, HG_SMEM_B>>>(
            ZtP[0], ZtP[1], GP[0], GP[1], NFEAT, MDICT, MDICT,
            pGZt, MDICT, NFEAT, MDICT, nullptr, nullptr, nullptr, 0, 0);
        k_update<<<NFEAT, 256>>>(coefs[it], it);
    }

    k_norms<<<1, 32>>>(o_nrm);
    k_transpose<<<dim3(MDICT / 32, NFEAT / 32), dim3(32, 8)>>>(pGmt, o_gam);
    k_pack<<<dim3(KB_MD, NFEAT / 32), 128>>>(pGmt, NFEAT, MDICT, MDICT, GmtP[0], GmtP[1], NFEAT);

    // ---- x_dec = W @ Gamma (fp32 to out + packed split) ----
    hgemm<12><<<dim3(32, 22), 256, HG_SMEM_B>>>(
        WP[0], WP[1], GmtP[0], GmtP[1], NPAD, NFEAT, MDICT,
        o_xdec, NFEAT, NNODES, NFEAT, nullptr, XdP[0], XdP[1], NPAD, 0);
    // ---- xg1 = x_dec @ gc1_w (packed transposed out only) ----
    hgemm<16><<<dim3(8, 22), 256, HG_SMEM_B>>>(
        XdP[0], XdP[1], G1wtP[0], G1wtP[1], NPAD, NHID, NFEAT,
        nullptr, 0, NNODES, NHID, nullptr, Xg1tP[0], Xg1tP[1], NHID, KNODE);
    // ---- h = relu(adj @ xg1 + b1) (packed split out) ----
    hgemm<11><<<dim3(8, 22), 256, HG_SMEM_B>>>(
        AdjP[0], AdjP[1], Xg1tP[0], Xg1tP[1], NPAD, NHID, KNODE,
        nullptr, 0, NNODES, NHID, g1b, HP[0], HP[1], NPAD, 0);
    // ---- hg2 = h @ gc2_w (packed transposed out) ----
    hgemm<16><<<dim3(1, 22), 256, HG_SMEM_B>>>(
        HP[0], HP[1], G2wtP[0], G2wtP[1], NPAD, 128, NHID,
        nullptr, 0, NNODES, NCLS, nullptr, Hg2tP[0], Hg2tP[1], 128, KNODE);
    // ---- out2 = adj @ hg2 + b2 (fp32) ----
    hgemm<5><<<dim3(1, 22), 256, HG_SMEM_B>>>(
        AdjP[0], AdjP[1], Hg2tP[0], Hg2tP[1], NPAD, 128, KNODE,
        po2, NCLS, NNODES, NCLS, g2b, nullptr, nullptr, 0, 0);

    k_logsm<<<NNODES, 32>>>(po2, o_logp);
}